// round 2
// baseline (speedup 1.0000x reference)
#include <cuda_runtime.h>
#include <cuda_bf16.h>
#include <math.h>
#include <stdint.h>

// Instant-NGP HashGrid encoding
//   x:     [N, 3]  float32, coords in [0,1)
//   table: [16, 2^19, 2] float32
//   out:   [N, 32] float32  (level-major pairs: out[p, l*2 + f])
//
// One thread per (point, level). 16 threads of a warp share a point; each
// thread does 8 hash-gathers (float2) + trilinear interp, writes one float2.
// Output stored with .cs (streaming) so the 128MB write stream doesn't evict
// the 64MB hash table from L2.

#define NGP_LEVELS 16
#define NGP_LOG2T  19
#define NGP_T      (1u << NGP_LOG2T)
#define NGP_TMASK  (NGP_T - 1u)

#define PRIME_Y 2654435761u
#define PRIME_Z 805459861u

struct ResArr { float r[NGP_LEVELS]; };

__device__ __forceinline__ void store_cs_f2(float2* p, float a, float b) {
    asm volatile("st.global.cs.v2.f32 [%0], {%1, %2};"
                 :: "l"(p), "f"(a), "f"(b) : "memory");
}

__global__ __launch_bounds__(256)
void ngp_hashgrid_kernel(const float* __restrict__ x,
                         const float* __restrict__ table,
                         float2* __restrict__ out,
                         ResArr res,
                         int n_points)
{
    int tid = blockIdx.x * blockDim.x + threadIdx.x;
    int point = tid >> 4;
    int level = tid & 15;
    if (point >= n_points) return;

    // coords (16 threads share a point -> L1 broadcast)
    const float cx = __ldg(x + point * 3 + 0);
    const float cy = __ldg(x + point * 3 + 1);
    const float cz = __ldg(x + point * 3 + 2);

    const float r = res.r[level];

    const float px = cx * r;
    const float py = cy * r;
    const float pz = cz * r;

    const float p0x = floorf(px);
    const float p0y = floorf(py);
    const float p0z = floorf(pz);

    const float fx = px - p0x;
    const float fy = py - p0y;
    const float fz = pz - p0z;

    const uint32_t ix = (uint32_t)p0x;
    const uint32_t iy = (uint32_t)p0y;
    const uint32_t iz = (uint32_t)p0z;

    // factored spatial hash: h = (x*1) ^ (y*PRIME_Y) ^ (z*PRIME_Z)
    const uint32_t hx0 = ix;
    const uint32_t hx1 = ix + 1u;
    const uint32_t hy0 = iy * PRIME_Y;
    const uint32_t hy1 = (iy + 1u) * PRIME_Y;
    const uint32_t hz0 = iz * PRIME_Z;
    const uint32_t hz1 = (iz + 1u) * PRIME_Z;

    const uint32_t m00 = hy0 ^ hz0;   // (y0, z0)
    const uint32_t m10 = hy1 ^ hz0;   // (y1, z0)
    const uint32_t m01 = hy0 ^ hz1;   // (y0, z1)
    const uint32_t m11 = hy1 ^ hz1;   // (y1, z1)

    const float2* __restrict__ tl =
        reinterpret_cast<const float2*>(table) + (uint32_t)level * NGP_T;

    // 8 independent gathers, issued back-to-back for MLP
    const float2 f000 = __ldg(tl + ((hx0 ^ m00) & NGP_TMASK));
    const float2 f100 = __ldg(tl + ((hx1 ^ m00) & NGP_TMASK));
    const float2 f010 = __ldg(tl + ((hx0 ^ m10) & NGP_TMASK));
    const float2 f110 = __ldg(tl + ((hx1 ^ m10) & NGP_TMASK));
    const float2 f001 = __ldg(tl + ((hx0 ^ m01) & NGP_TMASK));
    const float2 f101 = __ldg(tl + ((hx1 ^ m01) & NGP_TMASK));
    const float2 f011 = __ldg(tl + ((hx0 ^ m11) & NGP_TMASK));
    const float2 f111 = __ldg(tl + ((hx1 ^ m11) & NGP_TMASK));

    const float gx = 1.0f - fx;
    const float gy = 1.0f - fy;
    const float gz = 1.0f - fz;

    // corner c: x-bit = c&1, y-bit = (c>>1)&1, z-bit = (c>>2)&1
    const float wz0y0 = gy * gz;
    const float wz0y1 = fy * gz;
    const float wz1y0 = gy * fz;
    const float wz1y1 = fy * fz;

    const float w000 = gx * wz0y0;
    const float w100 = fx * wz0y0;
    const float w010 = gx * wz0y1;
    const float w110 = fx * wz0y1;
    const float w001 = gx * wz1y0;
    const float w101 = fx * wz1y0;
    const float w011 = gx * wz1y1;
    const float w111 = fx * wz1y1;

    float o0 = w000 * f000.x;
    float o1 = w000 * f000.y;
    o0 = fmaf(w100, f100.x, o0);  o1 = fmaf(w100, f100.y, o1);
    o0 = fmaf(w010, f010.x, o0);  o1 = fmaf(w010, f010.y, o1);
    o0 = fmaf(w110, f110.x, o0);  o1 = fmaf(w110, f110.y, o1);
    o0 = fmaf(w001, f001.x, o0);  o1 = fmaf(w001, f001.y, o1);
    o0 = fmaf(w101, f101.x, o0);  o1 = fmaf(w101, f101.y, o1);
    o0 = fmaf(w011, f011.x, o0);  o1 = fmaf(w011, f011.y, o1);
    o0 = fmaf(w111, f111.x, o0);  o1 = fmaf(w111, f111.y, o1);

    // out[point, level*2 .. level*2+1]: half-warp writes one 128B line.
    // Streaming store: output never re-read, keep L2 for the table.
    store_cs_f2(out + (uint32_t)point * NGP_LEVELS + (uint32_t)level, o0, o1);
}

extern "C" void kernel_launch(void* const* d_in, const int* in_sizes, int n_in,
                              void* d_out, int out_size)
{
    const float* x     = (const float*)d_in[0];
    const float* table = (const float*)d_in[1];
    float2* out        = (float2*)d_out;

    const int n_points = in_sizes[0] / 3;

    // Resolutions computed in double on host each call (deterministic).
    // Matches the f32 reference's floor on every level, incl. the
    // res15 = 4095 (NOT 4096) boundary: 16 * s^15 = 4095.99696.
    ResArr res;
    const double s = 1.4472692012786865;
    for (int l = 0; l < NGP_LEVELS; ++l) {
        res.r[l] = floorf((float)(16.0 * pow(s, (double)l)));
    }

    const int total   = n_points * NGP_LEVELS;
    const int threads = 256;
    const int blocks  = (total + threads - 1) / threads;

    ngp_hashgrid_kernel<<<blocks, threads>>>(x, table, out, res, n_points);
}